// round 16
// baseline (speedup 1.0000x reference)
#include <cuda_runtime.h>
#include <math.h>

#define BINS 50
#define MBINS (BINS * BINS)                  // 2500
#define JBINS (BINS * BINS * BINS * BINS)    // 6,250,000

// ---------------- device scratch (no allocations allowed) ----------------
// All state is restored to these initial values at the end of every
// kernel_launch execution (clear-on-read), so each graph replay is identical.
__device__ double   g_sums[14] = {};   // 0..3 sum x_i ; 4..13 upper-tri sum x_i x_j
__device__ double   g_entJ = 0.0;      // sum c*log(c) over joint hist
__device__ unsigned g_minq = 0xFFFFFFFFu, g_maxq = 0u;
__device__ unsigned g_minr = 0xFFFFFFFFu, g_maxr = 0u;
__device__ unsigned g_mins = 0xFFFFFFFFu, g_maxs = 0u;
__device__ unsigned g_done = 0;        // last-block detector for entJ
__device__ float    g_L[16];           // lower-tri cholesky factor (row major)
__device__ float    g_mean[4];
__device__ unsigned g_hist_joint[JBINS];   // 25 MB, starts zero, kept zero
__device__ unsigned g_hist_q[MBINS];
__device__ unsigned g_hist_r[MBINS];

// ---------------- helpers ----------------
__device__ __forceinline__ unsigned fenc(float f) {
    unsigned u = __float_as_uint(f);
    return (u & 0x80000000u) ? ~u : (u | 0x80000000u);
}
__device__ __forceinline__ float fdec(unsigned e) {
    unsigned u = (e & 0x80000000u) ? (e & 0x7fffffffu) : ~e;
    return __uint_as_float(u);
}
__device__ __forceinline__ int binof(float x, float lo, float scale) {
    int i = (int)floorf((x - lo) * scale);
    i = i < 0 ? 0 : i;
    return i > (BINS - 1) ? (BINS - 1) : i;
}

// ---------------- kernel 1: moments + min/max (fp32 accum, FMNMX min/max) ----------------
__global__ void __launch_bounds__(256) k_stats(const float2* __restrict__ q,
                                               const float2* __restrict__ r, int n) {
    int idx = blockIdx.x * blockDim.x + threadIdx.x;
    int stride = gridDim.x * blockDim.x;
    float s[14];
#pragma unroll
    for (int k = 0; k < 14; k++) s[k] = 0.0f;
    float mnq = 3.4e38f, mxq = -3.4e38f, mnr = 3.4e38f, mxr = -3.4e38f;

    for (int i = idx; i < n; i += stride) {
        float2 qv = q[i];
        float2 rv = r[i];
        float x0 = qv.x, x1 = qv.y, x2 = rv.x, x3 = rv.y;
        s[0] += x0; s[1] += x1; s[2] += x2; s[3] += x3;
        s[4]  = fmaf(x0, x0, s[4]);  s[5]  = fmaf(x0, x1, s[5]);
        s[6]  = fmaf(x0, x2, s[6]);  s[7]  = fmaf(x0, x3, s[7]);
        s[8]  = fmaf(x1, x1, s[8]);  s[9]  = fmaf(x1, x2, s[9]);
        s[10] = fmaf(x1, x3, s[10]); s[11] = fmaf(x2, x2, s[11]);
        s[12] = fmaf(x2, x3, s[12]); s[13] = fmaf(x3, x3, s[13]);
        mnq = fminf(mnq, fminf(x0, x1)); mxq = fmaxf(mxq, fmaxf(x0, x1));
        mnr = fminf(mnr, fminf(x2, x3)); mxr = fmaxf(mxr, fmaxf(x2, x3));
    }

    const unsigned FULL = 0xFFFFFFFFu;
#pragma unroll
    for (int off = 16; off; off >>= 1) {
#pragma unroll
        for (int k = 0; k < 14; k++) s[k] += __shfl_down_sync(FULL, s[k], off);
        mnq = fminf(mnq, __shfl_down_sync(FULL, mnq, off));
        mxq = fmaxf(mxq, __shfl_down_sync(FULL, mxq, off));
        mnr = fminf(mnr, __shfl_down_sync(FULL, mnr, off));
        mxr = fmaxf(mxr, __shfl_down_sync(FULL, mxr, off));
    }

    __shared__ double sh[8][14];
    __shared__ float  shm[8][4];
    int wid = threadIdx.x >> 5, lane = threadIdx.x & 31;
    if (lane == 0) {
#pragma unroll
        for (int k = 0; k < 14; k++) sh[wid][k] = (double)s[k];
        shm[wid][0] = mnq; shm[wid][1] = mxq; shm[wid][2] = mnr; shm[wid][3] = mxr;
    }
    __syncthreads();
    if (threadIdx.x < 14) {
        int k = threadIdx.x;
        double acc = sh[0][k];
#pragma unroll
        for (int w = 1; w < 8; w++) acc += sh[w][k];
        atomicAdd(&g_sums[k], acc);
    } else if (threadIdx.x == 32) {
        float a = shm[0][0], b = shm[0][1], c = shm[0][2], d = shm[0][3];
#pragma unroll
        for (int w = 1; w < 8; w++) {
            a = fminf(a, shm[w][0]); b = fmaxf(b, shm[w][1]);
            c = fminf(c, shm[w][2]); d = fmaxf(d, shm[w][3]);
        }
        atomicMin(&g_minq, fenc(a)); atomicMax(&g_maxq, fenc(b));
        atomicMin(&g_minr, fenc(c)); atomicMax(&g_maxr, fenc(d));
    }
}

// mean, covariance (+eps*I), fp32 cholesky — runs on ONE thread inside margHist
__device__ void do_cholesky(int n) {
    double shs[14];
#pragma unroll
    for (int k = 0; k < 14; k++) shs[k] = g_sums[k];
    double nn = (double)n;
    double mean[4];
#pragma unroll
    for (int i = 0; i < 4; i++) mean[i] = shs[i] / nn;
    float cov[4][4];
    int idx = 4;
#pragma unroll
    for (int i = 0; i < 4; i++)
#pragma unroll
        for (int j = i; j < 4; j++) {
            float c = (float)((shs[idx++] - nn * mean[i] * mean[j]) / (nn - 1.0));
            cov[i][j] = c; cov[j][i] = c;
        }
#pragma unroll
    for (int i = 0; i < 4; i++) cov[i][i] += 1e-6f;

    float L[4][4] = {};
#pragma unroll
    for (int j = 0; j < 4; j++) {
        float d = cov[j][j];
#pragma unroll
        for (int k = 0; k < 4; k++) if (k < j) d -= L[j][k] * L[j][k];
        float dj = sqrtf(d);
        L[j][j] = dj;
        float inv = __frcp_rn(dj);
#pragma unroll
        for (int i = 0; i < 4; i++) if (i > j) {
            float v = cov[i][j];
#pragma unroll
            for (int k = 0; k < 4; k++) if (k < j) v -= L[i][k] * L[j][k];
            L[i][j] = v * inv;
        }
    }
#pragma unroll
    for (int i = 0; i < 4; i++) {
        g_mean[i] = (float)mean[i];
#pragma unroll
        for (int j = 0; j < 4; j++) g_L[i * 4 + j] = L[i][j];
    }
}

// ---------------- kernel 2: marginal histograms + (block0) cholesky ----------------
__global__ void __launch_bounds__(256) k_margHist(const float2* __restrict__ q,
                                                  const float2* __restrict__ r, int n) {
    __shared__ unsigned shq[MBINS];
    __shared__ unsigned shr[MBINS];
    for (int i = threadIdx.x; i < MBINS; i += blockDim.x) { shq[i] = 0u; shr[i] = 0u; }
    __syncthreads();

    if (blockIdx.x == 0 && threadIdx.x == 0) do_cholesky(n);

    float loq = fdec(g_minq), hiq = fdec(g_maxq);
    float lor = fdec(g_minr), hir = fdec(g_maxr);
    float sq = (float)BINS / (hiq - loq);
    float sr = (float)BINS / (hir - lor);

    int idx = blockIdx.x * blockDim.x + threadIdx.x;
    int stride = gridDim.x * blockDim.x;
    for (int i = idx; i < n; i += stride) {
        float2 qv = q[i];
        atomicAdd(&shq[binof(qv.x, loq, sq) * BINS + binof(qv.y, loq, sq)], 1u);
        float2 rv = r[i];
        atomicAdd(&shr[binof(rv.x, lor, sr) * BINS + binof(rv.y, lor, sr)], 1u);
    }
    __syncthreads();
    for (int i = threadIdx.x; i < MBINS; i += blockDim.x) {
        unsigned a = shq[i]; if (a) atomicAdd(&g_hist_q[i], a);
        unsigned b = shr[i]; if (b) atomicAdd(&g_hist_r[i], b);
    }
}

__device__ __forceinline__ void transform_row(float4 zv, const float* L, const float* m,
                                              float& s0, float& s1, float& s2, float& s3) {
    s0 = fmaf(zv.x, L[0], m[0]);
    s1 = fmaf(zv.y, L[5],  fmaf(zv.x, L[4],  m[1]));
    s2 = fmaf(zv.z, L[10], fmaf(zv.y, L[9],  fmaf(zv.x, L[8],  m[2])));
    s3 = fmaf(zv.w, L[15], fmaf(zv.z, L[14], fmaf(zv.y, L[13], fmaf(zv.x, L[12], m[3]))));
}

// ---------------- kernel 3: transform + global min/max (float FMNMX, MLP=8) ----------------
__global__ void __launch_bounds__(256) k_tmm(const float4* __restrict__ z, int S) {
    float L[16], m[4];
#pragma unroll
    for (int i = 0; i < 16; i++) L[i] = g_L[i];
#pragma unroll
    for (int i = 0; i < 4; i++) m[i] = g_mean[i];

    float fmn = 3.4e38f, fmx = -3.4e38f;
    int idx = blockIdx.x * blockDim.x + threadIdx.x;
    int stride = gridDim.x * blockDim.x;

    int i = idx;
    for (; i + 7 * stride < S; i += 8 * stride) {
        float4 v[8];
#pragma unroll
        for (int k = 0; k < 8; k++) v[k] = z[i + k * stride];
#pragma unroll
        for (int k = 0; k < 8; k++) {
            float s0, s1, s2, s3;
            transform_row(v[k], L, m, s0, s1, s2, s3);
            fmn = fminf(fmn, fminf(fminf(s0, s1), fminf(s2, s3)));
            fmx = fmaxf(fmx, fmaxf(fmaxf(s0, s1), fmaxf(s2, s3)));
        }
    }
    for (; i + 3 * stride < S; i += 4 * stride) {
        float4 v[4];
#pragma unroll
        for (int k = 0; k < 4; k++) v[k] = z[i + k * stride];
#pragma unroll
        for (int k = 0; k < 4; k++) {
            float s0, s1, s2, s3;
            transform_row(v[k], L, m, s0, s1, s2, s3);
            fmn = fminf(fmn, fminf(fminf(s0, s1), fminf(s2, s3)));
            fmx = fmaxf(fmx, fmaxf(fmaxf(s0, s1), fmaxf(s2, s3)));
        }
    }
    for (; i < S; i += stride) {
        float s0, s1, s2, s3;
        transform_row(z[i], L, m, s0, s1, s2, s3);
        fmn = fminf(fmn, fminf(fminf(s0, s1), fminf(s2, s3)));
        fmx = fmaxf(fmx, fmaxf(fmaxf(s0, s1), fmaxf(s2, s3)));
    }

    const unsigned FULL = 0xFFFFFFFFu;
    for (int off = 16; off; off >>= 1) {
        fmn = fminf(fmn, __shfl_down_sync(FULL, fmn, off));
        fmx = fmaxf(fmx, __shfl_down_sync(FULL, fmx, off));
    }
    __shared__ float shmn[8], shmx[8];
    int wid = threadIdx.x >> 5, lane = threadIdx.x & 31;
    if (lane == 0) { shmn[wid] = fmn; shmx[wid] = fmx; }
    __syncthreads();
    if (threadIdx.x == 0) {
        int nw = blockDim.x >> 5;
        for (int w = 1; w < nw; w++) { fmn = fminf(fmn, shmn[w]); fmx = fmaxf(fmx, shmx[w]); }
        atomicMin(&g_mins, fenc(fmn));
        atomicMax(&g_maxs, fenc(fmx));
    }
}

// ---------------- kernel 4: joint histogram (R13 body, frozen) ----------------
__global__ void __launch_bounds__(256) k_jhist(const float4* __restrict__ z, int S) {
    float L[16], m[4];
#pragma unroll
    for (int i = 0; i < 16; i++) L[i] = g_L[i];
#pragma unroll
    for (int i = 0; i < 4; i++) m[i] = g_mean[i];
    float lo = fdec(g_mins), hi = fdec(g_maxs);
    float sc = (float)BINS / (hi - lo);

    int idx = blockIdx.x * blockDim.x + threadIdx.x;
    int stride = gridDim.x * blockDim.x;

    int i = idx;
    for (; i + 3 * stride < S; i += 4 * stride) {
        float4 a = z[i];
        float4 b = z[i + stride];
        float4 c = z[i + 2 * stride];
        float4 d = z[i + 3 * stride];
        float s0, s1, s2, s3;
        transform_row(a, L, m, s0, s1, s2, s3);
        int fa = ((binof(s0, lo, sc) * BINS + binof(s1, lo, sc)) * BINS +
                  binof(s2, lo, sc)) * BINS + binof(s3, lo, sc);
        transform_row(b, L, m, s0, s1, s2, s3);
        int fb = ((binof(s0, lo, sc) * BINS + binof(s1, lo, sc)) * BINS +
                  binof(s2, lo, sc)) * BINS + binof(s3, lo, sc);
        transform_row(c, L, m, s0, s1, s2, s3);
        int fc = ((binof(s0, lo, sc) * BINS + binof(s1, lo, sc)) * BINS +
                  binof(s2, lo, sc)) * BINS + binof(s3, lo, sc);
        transform_row(d, L, m, s0, s1, s2, s3);
        int fd = ((binof(s0, lo, sc) * BINS + binof(s1, lo, sc)) * BINS +
                  binof(s2, lo, sc)) * BINS + binof(s3, lo, sc);
        atomicAdd(&g_hist_joint[fa], 1u);
        atomicAdd(&g_hist_joint[fb], 1u);
        atomicAdd(&g_hist_joint[fc], 1u);
        atomicAdd(&g_hist_joint[fd], 1u);
    }
    for (; i < S; i += stride) {
        float s0, s1, s2, s3;
        transform_row(z[i], L, m, s0, s1, s2, s3);
        int flat = ((binof(s0, lo, sc) * BINS + binof(s1, lo, sc)) * BINS +
                    binof(s2, lo, sc)) * BINS + binof(s3, lo, sc);
        atomicAdd(&g_hist_joint[flat], 1u);
    }
}

// ---------------- kernel 5: joint entropy + finalization (R13 body, frozen) ----------------
__device__ __forceinline__ double qsum(uint4 v) {
    float a = v.x ? (float)v.x * __logf((float)v.x) : 0.0f;
    float b = v.y ? (float)v.y * __logf((float)v.y) : 0.0f;
    float c = v.z ? (float)v.z * __logf((float)v.z) : 0.0f;
    float d = v.w ? (float)v.w * __logf((float)v.w) : 0.0f;
    return ((double)a + (double)b) + ((double)c + (double)d);
}

__global__ void __launch_bounds__(256) k_entJ(float* out, int n, int S) {
    double a0 = 0.0, a1 = 0.0, a2 = 0.0, a3 = 0.0;
    uint4* p = (uint4*)g_hist_joint;
    const uint4 zero = make_uint4(0u, 0u, 0u, 0u);
    const int Q = JBINS / 4;
    int idx = blockIdx.x * blockDim.x + threadIdx.x;
    int stride = gridDim.x * blockDim.x;

    int i = idx;
    for (; i + 3 * stride < Q; i += 4 * stride) {
        uint4 a = p[i];
        uint4 b = p[i + stride];
        uint4 c = p[i + 2 * stride];
        uint4 d = p[i + 3 * stride];
        if (a.x | a.y | a.z | a.w) { a0 += qsum(a); p[i] = zero; }
        if (b.x | b.y | b.z | b.w) { a1 += qsum(b); p[i + stride] = zero; }
        if (c.x | c.y | c.z | c.w) { a2 += qsum(c); p[i + 2 * stride] = zero; }
        if (d.x | d.y | d.z | d.w) { a3 += qsum(d); p[i + 3 * stride] = zero; }
    }
    for (; i < Q; i += stride) {
        uint4 v = p[i];
        if (v.x | v.y | v.z | v.w) { a0 += qsum(v); p[i] = zero; }
    }
    double sum = (a0 + a1) + (a2 + a3);

    const unsigned FULL = 0xFFFFFFFFu;
    for (int off = 16; off; off >>= 1) sum += __shfl_down_sync(FULL, sum, off);
    __shared__ double sh[8];
    __shared__ int s_last;
    int wid = threadIdx.x >> 5, lane = threadIdx.x & 31;
    if (lane == 0) sh[wid] = sum;
    __syncthreads();
    if (threadIdx.x == 0) {
        int nw = blockDim.x >> 5;
        for (int w = 1; w < nw; w++) sum += sh[w];
        atomicAdd(&g_entJ, sum);
        __threadfence();
        unsigned t = atomicAdd(&g_done, 1u);
        s_last = (t == gridDim.x - 1) ? 1 : 0;
    }
    __syncthreads();
    if (!s_last) return;

    // ---- last block: marginal entropies + final scalar + state reset ----
    __threadfence();
    double sq = 0.0, sr = 0.0;
    for (int k = threadIdx.x; k < MBINS; k += blockDim.x) {
        unsigned a = g_hist_q[k]; if (a) { sq += (double)a * (double)logf((float)a); g_hist_q[k] = 0u; }
        unsigned b = g_hist_r[k]; if (b) { sr += (double)b * (double)logf((float)b); g_hist_r[k] = 0u; }
    }
    for (int off = 16; off; off >>= 1) {
        sq += __shfl_down_sync(FULL, sq, off);
        sr += __shfl_down_sync(FULL, sr, off);
    }
    __shared__ double shq[8], shr[8];
    if (lane == 0) { shq[wid] = sq; shr[wid] = sr; }
    __syncthreads();
    if (threadIdx.x == 0) {
        int nw = blockDim.x >> 5;
        for (int w = 1; w < nw; w++) { sq += shq[w]; sr += shr[w]; }
        double nn = (double)n, SS = (double)S;
        double H_T = log(nn) - sq / nn;
        double H_I = log(nn) - sr / nn;
        double H_J = log(SS) - g_entJ / SS;
        double v = H_J / (H_T + H_I);
        v = v < 0.0 ? 0.0 : (v > 1.0 ? 1.0 : v);
        out[0] = (float)v;

        // restore scalar state for the next replay
        g_entJ = 0.0;
#pragma unroll
        for (int k = 0; k < 14; k++) g_sums[k] = 0.0;
        g_minq = 0xFFFFFFFFu; g_maxq = 0u;
        g_minr = 0xFFFFFFFFu; g_maxr = 0u;
        g_mins = 0xFFFFFFFFu; g_maxs = 0u;
        g_done = 0u;
    }
}

// ---------------- launch ----------------
extern "C" void kernel_launch(void* const* d_in, const int* in_sizes, int n_in,
                              void* d_out, int out_size) {
    const float* q = (const float*)d_in[0];
    const float* r = (const float*)d_in[1];
    const float* z = (const float*)d_in[2];
    int n = in_sizes[0] / 2;   // 200000 rows of D=2
    int S = in_sizes[2] / 4;   // 2000000 rows of 2D=4

    k_stats<<<592, 256>>>((const float2*)q, (const float2*)r, n);
    k_margHist<<<128, 256>>>((const float2*)q, (const float2*)r, n);
    k_tmm<<<592, 256>>>((const float4*)z, S);
    k_jhist<<<592, 256>>>((const float4*)z, S);
    k_entJ<<<592, 256>>>((float*)d_out, n, S);
}